// round 3
// baseline (speedup 1.0000x reference)
#include <cuda_runtime.h>
#include <cuda_bf16.h>
#include <math.h>

#define N_   2
#define H_   96
#define W_   96
#define HWp  9216      // H_*W_
#define CH_  64

// ---------------- scratch (device globals; allocation-free) ----------------
__device__ float g_xh  [N_*CH_*HWp];
__device__ float g_om  [N_*27 *HWp];
__device__ float g_z   [N_*CH_*HWp];
__device__ float g_r   [N_*CH_*HWp];
__device__ float g_xenh[N_*CH_*HWp];

// ============================================================================
// conv3x3, SAME padding, NCHW. Input may be a channel-concat of two tensors:
// channels [0,CA) from inA, [CA,CIN) from inB.
// Block: 128 threads, 32x16 spatial tile, 8 output channels.
// Each thread: 4 vertically adjacent pixels.
// ============================================================================
template<int CIN, int CA>
__global__ __launch_bounds__(128)
void conv3x3_kernel(const float* __restrict__ inA, const float* __restrict__ inB,
                    const float* __restrict__ wt, const float* __restrict__ bias,
                    float* __restrict__ out, int COUT)
{
    const int tile = blockIdx.x;            // 18 tiles (3 x, 6 y)
    const int co0  = blockIdx.y * 8;
    const int n    = blockIdx.z;
    const int tx0  = (tile % 3) * 32;
    const int ty0  = (tile / 3) * 16;
    const int tid  = threadIdx.x;
    const int lx   = tid & 31;
    const int ry   = (tid >> 5) * 4;        // local row base (0,4,8,12)

    __shared__ float sPatch[2][18][36];     // rows -1..16, cols -1..32 (padded)
    __shared__ float sW[2][8][9];

    float acc[8][4];
#pragma unroll
    for (int i = 0; i < 8; i++)
#pragma unroll
        for (int j = 0; j < 4; j++) acc[i][j] = 0.f;

    for (int ci0 = 0; ci0 < CIN; ci0 += 2) {
        __syncthreads();
        // load 2 input patches (2*18*34 = 1224 elems)
#pragma unroll
        for (int it = 0; it < 10; it++) {
            unsigned idx = tid + it * 128u;
            if (idx < 1224u) {
                unsigned cc  = idx / 612u;
                unsigned rem = idx - cc * 612u;
                unsigned rr  = rem / 34u;
                unsigned col = rem - rr * 34u;
                int gy = ty0 + (int)rr - 1;
                int gx = tx0 + (int)col - 1;
                float v = 0.f;
                if (gy >= 0 && gy < H_ && gx >= 0 && gx < W_) {
                    int c = ci0 + (int)cc;
                    const float* src = (c < CA)
                        ? inA + ((size_t)n * CA + c) * HWp
                        : inB + ((size_t)n * (CIN - CA) + (c - CA)) * HWp;
                    v = src[gy * W_ + gx];
                }
                sPatch[cc][rr][col] = v;
            }
        }
        // load weights: 2*8*9 = 144 elems
        for (int i = tid; i < 144; i += 128) {
            int cc  = i / 72;
            int rem = i - cc * 72;
            int co  = rem / 9;
            int k   = rem - co * 9;
            float wv = 0.f;
            if (co0 + co < COUT)
                wv = wt[((size_t)(co0 + co) * CIN + ci0 + cc) * 9 + k];
            sW[cc][co][k] = wv;
        }
        __syncthreads();

#pragma unroll
        for (int cc = 0; cc < 2; cc++) {
            float p[6][3];
#pragma unroll
            for (int dr = 0; dr < 6; dr++)
#pragma unroll
                for (int dc = 0; dc < 3; dc++)
                    p[dr][dc] = sPatch[cc][ry + dr][lx + dc];
#pragma unroll
            for (int co = 0; co < 8; co++) {
#pragma unroll
                for (int ky = 0; ky < 3; ky++)
#pragma unroll
                    for (int kx = 0; kx < 3; kx++) {
                        float wv = sW[cc][co][ky * 3 + kx];
#pragma unroll
                        for (int px = 0; px < 4; px++)
                            acc[co][px] += wv * p[px + ky][kx];
                    }
            }
        }
    }

#pragma unroll
    for (int co = 0; co < 8; co++) {
        if (co0 + co < COUT) {
            float b = bias[co0 + co];
#pragma unroll
            for (int px = 0; px < 4; px++) {
                int gy = ty0 + ry + px;
                out[(((size_t)n * COUT + co0 + co) * H_ + gy) * W_ + tx0 + lx] = acc[co][px] + b;
            }
        }
    }
}

// ============================================================================
// Deformable conv main pass, fused with gate epilogues.
// Input: 128-channel concat (inA: ch 0..63, inB: ch 64..127).
// om: (n,27,H,W)  dy = om[0:9], dx = om[9:18], mask = sigmoid(om[18:27]).
// wt: (64,128,9).  MODE 0: out = sigmoid(acc+b)   (z gate)
//                  MODE 1: out = (1-z)*t + z*tanh(acc+b)  (GRU blend)
// Block: 128 threads = 16x8 pixel tile; 8 output channels per block.
// ============================================================================
template<int MODE>
__global__ __launch_bounds__(128)
void dcn_kernel(const float* __restrict__ inA, const float* __restrict__ inB,
                const float* __restrict__ om,
                const float* __restrict__ wt, const float* __restrict__ bias,
                const float* __restrict__ tbuf, const float* __restrict__ zbuf,
                float* __restrict__ out)
{
    const int n    = blockIdx.z;
    const int co0  = blockIdx.y * 8;
    const int tile = blockIdx.x;            // 72 tiles (6 x, 12 y)
    const int tx0  = (tile % 6) * 16;
    const int ty0  = (tile / 6) * 8;
    const int tid  = threadIdx.x;
    const int x    = tx0 + (tid & 15);
    const int y    = ty0 + (tid >> 4);
    const int p    = y * W_ + x;

    __shared__ float sW[8 * 128 * 9];       // 36 KB
    {
        const float* wsrc = wt + (size_t)co0 * 128 * 9;
        for (int i = tid; i < 8 * 128 * 9; i += 128) sW[i] = wsrc[i];
    }
    __syncthreads();

    float acc[8];
#pragma unroll
    for (int i = 0; i < 8; i++) acc[i] = 0.f;

    const float* baseOm = om + (size_t)n * 27 * HWp + p;
    const float* pA = inA + (size_t)n * 64 * HWp;
    const float* pB = inB + (size_t)n * 64 * HWp;

#pragma unroll
    for (int k = 0; k < 9; k++) {
        const int ky = k / 3 - 1;
        const int kx = k % 3 - 1;
        float dy = baseOm[(size_t)k * HWp];
        float dx = baseOm[(size_t)(9 + k) * HWp];
        float mm = baseOm[(size_t)(18 + k) * HWp];
        float mask = 1.f / (1.f + __expf(-mm));

        float py = (float)(y + ky) + dy;
        float px = (float)(x + kx) + dx;
        float y0f = floorf(py), x0f = floorf(px);
        float wy = py - y0f, wx = px - x0f;
        int y0 = (int)y0f, x0 = (int)x0f;
        int y1 = y0 + 1, x1 = x0 + 1;
        bool vy0 = (y0 >= 0) & (y0 < H_);
        bool vy1 = (y1 >= 0) & (y1 < H_);
        bool vx0 = (x0 >= 0) & (x0 < W_);
        bool vx1 = (x1 >= 0) & (x1 < W_);
        int yc0 = min(max(y0, 0), H_ - 1), yc1 = min(max(y1, 0), H_ - 1);
        int xc0 = min(max(x0, 0), W_ - 1), xc1 = min(max(x1, 0), W_ - 1);
        int i00 = yc0 * W_ + xc0, i01 = yc0 * W_ + xc1;
        int i10 = yc1 * W_ + xc0, i11 = yc1 * W_ + xc1;
        float w00 = (vy0 & vx0) ? (1.f - wy) * (1.f - wx) * mask : 0.f;
        float w01 = (vy0 & vx1) ? (1.f - wy) * wx * mask : 0.f;
        float w10 = (vy1 & vx0) ? wy * (1.f - wx) * mask : 0.f;
        float w11 = (vy1 & vx1) ? wy * wx * mask : 0.f;

        // channels 0..63 (inA)
        {
            const float* a00 = pA + i00; const float* a01 = pA + i01;
            const float* a10 = pA + i10; const float* a11 = pA + i11;
            const float* wp  = sW + k;
#pragma unroll 4
            for (int c = 0; c < 64; c++) {
                float s = w00 * a00[(size_t)c * HWp] + w01 * a01[(size_t)c * HWp]
                        + w10 * a10[(size_t)c * HWp] + w11 * a11[(size_t)c * HWp];
#pragma unroll
                for (int co = 0; co < 8; co++)
                    acc[co] += wp[(co * 128 + c) * 9] * s;
            }
        }
        // channels 64..127 (inB)
        {
            const float* a00 = pB + i00; const float* a01 = pB + i01;
            const float* a10 = pB + i10; const float* a11 = pB + i11;
            const float* wp  = sW + 64 * 9 + k;
#pragma unroll 4
            for (int c = 0; c < 64; c++) {
                float s = w00 * a00[(size_t)c * HWp] + w01 * a01[(size_t)c * HWp]
                        + w10 * a10[(size_t)c * HWp] + w11 * a11[(size_t)c * HWp];
#pragma unroll
                for (int co = 0; co < 8; co++)
                    acc[co] += wp[(co * 128 + c) * 9] * s;
            }
        }
    }

#pragma unroll
    for (int co = 0; co < 8; co++) {
        float v = acc[co] + bias[co0 + co];
        size_t oi = ((size_t)n * 64 + co0 + co) * HWp + p;
        if (MODE == 0) {
            out[oi] = 1.f / (1.f + __expf(-v));
        } else {
            float zv = zbuf[oi];
            float tv = tbuf[oi];
            out[oi] = (1.f - zv) * tv + zv * tanhf(v);
        }
    }
}

// ============================================================================
// ncf: 7x7 (radius 3, dilation 2) normalized correlation + softmax + sample.
// f1, f2: (n,64,H,W). r: (n,64,H,W).  One thread per pixel.
// ============================================================================
__global__ __launch_bounds__(128)
void ncf_kernel(const float* __restrict__ f1, const float* __restrict__ f2,
                float* __restrict__ r)
{
    const int n    = blockIdx.y;
    const int tile = blockIdx.x;            // 72 tiles (6 x, 12 y)
    const int tx0  = (tile % 6) * 16;
    const int ty0  = (tile / 6) * 8;
    const int tid  = threadIdx.x;
    const int x    = tx0 + (tid & 15);
    const int y    = ty0 + (tid >> 4);
    const int p    = y * W_ + x;

    const float* F1 = f1 + (size_t)n * 64 * HWp;
    const float* F2 = f2 + (size_t)n * 64 * HWp;

    int idxK[49];
    float corr[49];
    unsigned long long vmask = 0ull;
#pragma unroll
    for (int k = 0; k < 49; k++) {
        int di = (k / 7) * 2 - 6;
        int dj = (k % 7) * 2 - 6;
        int yy = y + di, xx = x + dj;
        bool v = (yy >= 0) & (yy < H_) & (xx >= 0) & (xx < W_);
        int yc = min(max(yy, 0), H_ - 1);
        int xc = min(max(xx, 0), W_ - 1);
        idxK[k] = yc * W_ + xc;
        vmask |= (v ? 1ull : 0ull) << k;
        corr[k] = 0.f;
    }

    // phase 1: correlation
    for (int c = 0; c < 64; c++) {
        float f1v = F1[(size_t)c * HWp + p];
        const float* pl = F2 + (size_t)c * HWp;
#pragma unroll
        for (int k = 0; k < 49; k++)
            corr[k] += f1v * pl[idxK[k]];
    }

    // softmax over 49 (invalid taps contribute corr=0 — zeros in padded patch)
    const float scale = 0.125f;  // 1/sqrt(64)
    float m = -1e30f;
#pragma unroll
    for (int k = 0; k < 49; k++) {
        corr[k] = ((vmask >> k) & 1ull) ? corr[k] * scale : 0.f;
        m = fmaxf(m, corr[k]);
    }
    float sum = 0.f;
#pragma unroll
    for (int k = 0; k < 49; k++) {
        float e = __expf(corr[k] - m);
        corr[k] = e;
        sum += e;
    }
    float inv = 1.f / sum;
#pragma unroll
    for (int k = 0; k < 49; k++)
        corr[k] = ((vmask >> k) & 1ull) ? corr[k] * inv : 0.f;  // invalid taps sample zeros

    // phase 2: weighted sample
    for (int c = 0; c < 64; c++) {
        const float* pl = F2 + (size_t)c * HWp;
        float s = 0.f;
#pragma unroll
        for (int k = 0; k < 49; k++)
            s += corr[k] * pl[idxK[k]];
        r[((size_t)n * 64 + c) * HWp + p] = s;
    }
}

// ============================================================================
// launch
// ============================================================================
extern "C" void kernel_launch(void* const* d_in, const int* in_sizes, int n_in,
                              void* d_out, int out_size)
{
    (void)in_sizes; (void)n_in; (void)out_size;
    const float* x    = (const float*)d_in[0];
    const float* tmpl = (const float*)d_in[1];
    const float* w_in = (const float*)d_in[2];
    const float* b_in = (const float*)d_in[3];
    const float* w_out= (const float*)d_in[4];
    const float* b_out= (const float*)d_in[5];
    const float* ezw  = (const float*)d_in[6];
    const float* ezb  = (const float*)d_in[7];
    const float* ezow = (const float*)d_in[8];
    const float* ezob = (const float*)d_in[9];
    const float* ehw  = (const float*)d_in[10];
    const float* ehb  = (const float*)d_in[11];
    const float* ehow = (const float*)d_in[12];
    const float* ehob = (const float*)d_in[13];
    const float* uzw  = (const float*)d_in[14];
    const float* uzb  = (const float*)d_in[15];
    const float* uzow = (const float*)d_in[16];
    const float* uzob = (const float*)d_in[17];
    const float* uhw  = (const float*)d_in[18];
    const float* uhb  = (const float*)d_in[19];
    const float* uhow = (const float*)d_in[20];
    const float* uhob = (const float*)d_in[21];

    float *xh, *om, *z, *r, *xenh;
    cudaGetSymbolAddress((void**)&xh,   g_xh);
    cudaGetSymbolAddress((void**)&om,   g_om);
    cudaGetSymbolAddress((void**)&z,    g_z);
    cudaGetSymbolAddress((void**)&r,    g_r);
    cudaGetSymbolAddress((void**)&xenh, g_xenh);

    float* out_main = (float*)d_out;                       // (2,256,96,96)
    float* out_nt   = out_main + (size_t)N_ * 256 * HWp;   // (2,64,96,96)

    dim3 blk(128);

    // xh = conv_in(x)
    conv3x3_kernel<256,256><<<dim3(18, 8, 2), blk>>>(x, x, w_in, b_in, xh, 64);

    // ---- stargru enh: x = template, t = xh ----
    conv3x3_kernel<128,64><<<dim3(18, 4, 2), blk>>>(tmpl, xh, ezow, ezob, om, 27);
    dcn_kernel<0><<<dim3(72, 8, 2), blk>>>(tmpl, xh, om, ezw, ezb, nullptr, nullptr, z);
    ncf_kernel<<<dim3(72, 2), blk>>>(xh, tmpl, r);
    conv3x3_kernel<128,64><<<dim3(18, 4, 2), blk>>>(r, xh, ehow, ehob, om, 27);
    dcn_kernel<1><<<dim3(72, 8, 2), blk>>>(r, xh, om, ehw, ehb, xh, z, xenh);

    // ---- stargru upd: x = xh, t = template ----
    conv3x3_kernel<128,64><<<dim3(18, 4, 2), blk>>>(xh, tmpl, uzow, uzob, om, 27);
    dcn_kernel<0><<<dim3(72, 8, 2), blk>>>(xh, tmpl, om, uzw, uzb, nullptr, nullptr, z);
    ncf_kernel<<<dim3(72, 2), blk>>>(tmpl, xh, r);
    conv3x3_kernel<128,64><<<dim3(18, 4, 2), blk>>>(r, tmpl, uhow, uhob, om, 27);
    dcn_kernel<1><<<dim3(72, 8, 2), blk>>>(r, tmpl, om, uhw, uhb, tmpl, z, out_nt);

    // out = conv_out(x_enh)
    conv3x3_kernel<64,64><<<dim3(18, 32, 2), blk>>>(xenh, xenh, w_out, b_out, out_main, 256);
}

// round 4
// speedup vs baseline: 1.2521x; 1.2521x over previous
#include <cuda_runtime.h>
#include <cuda_bf16.h>
#include <math.h>

#define N_   2
#define H_   96
#define W_   96
#define HWp  9216      // H_*W_
#define CH_  64

typedef unsigned long long u64;

__device__ __forceinline__ u64 pack2(float lo, float hi) {
    u64 r; asm("mov.b64 %0, {%1, %2};" : "=l"(r) : "f"(lo), "f"(hi)); return r;
}
__device__ __forceinline__ void ffma2(u64 &d, u64 a, u64 b) {
    asm("fma.rn.f32x2 %0, %1, %2, %0;" : "+l"(d) : "l"(a), "l"(b));
}
__device__ __forceinline__ float2 unpack2(u64 v) {
    float2 f; asm("mov.b64 {%0, %1}, %2;" : "=f"(f.x), "=f"(f.y) : "l"(v)); return f;
}

// ---------------- scratch (device globals; allocation-free) ----------------
__device__ float g_xh  [N_*CH_*HWp];
__device__ float g_om  [N_*27 *HWp];
__device__ float g_z   [N_*CH_*HWp];
__device__ float g_r   [N_*CH_*HWp];
__device__ float g_xenh[N_*CH_*HWp];

// ============================================================================
// conv3x3, SAME padding, NCHW, f32x2-packed over cout pairs.
// Input = channel-concat: [0,CA) from inA, [CA,CIN) from inB.
// Block: 128 threads, 32x8 spatial tile, 8 output channels (4 pairs).
// Each thread: 2 vertically adjacent pixels. 4 input channels per stage.
// ============================================================================
template<int CIN, int CA>
__global__ __launch_bounds__(128)
void conv3x3_kernel(const float* __restrict__ inA, const float* __restrict__ inB,
                    const float* __restrict__ wt, const float* __restrict__ bias,
                    float* __restrict__ out, int COUT)
{
    const int tile = blockIdx.x;            // 36 tiles: 3 x, 12 y
    const int co0  = blockIdx.y * 8;
    const int n    = blockIdx.z;
    const int tx0  = (tile % 3) * 32;
    const int ty0  = (tile / 3) * 8;
    const int tid  = threadIdx.x;
    const int lx   = tid & 31;
    const int ry   = (tid >> 5) * 2;        // local out-row base (0,2,4,6)

    __shared__ float  sPatch[4][10][36];    // rows -1..8, cols -1..32 (padded)
    __shared__ float2 sW2[4][9][4];         // [cc][k][co_pair], co-pairs packed

    u64 acc2[4][2];
#pragma unroll
    for (int i = 0; i < 4; i++) { acc2[i][0] = 0ull; acc2[i][1] = 0ull; }

    for (int ci0 = 0; ci0 < CIN; ci0 += 4) {
        __syncthreads();
        // patch: 4 ch * 10 rows * 34 cols = 1360
#pragma unroll
        for (int it = 0; it < 11; it++) {
            int idx = tid + it * 128;
            if (idx < 1360) {
                int cc  = idx / 340;
                int rem = idx - cc * 340;
                int rr  = rem / 34;
                int col = rem - rr * 34;
                int gy = ty0 + rr - 1;
                int gx = tx0 + col - 1;
                float v = 0.f;
                if ((unsigned)gy < (unsigned)H_ && (unsigned)gx < (unsigned)W_) {
                    int c = ci0 + cc;
                    const float* src = (c < CA)
                        ? inA + ((size_t)n * CA + c) * HWp
                        : inB + ((size_t)n * (CIN - CA) + (c - CA)) * HWp;
                    v = src[gy * W_ + gx];
                }
                sPatch[cc][rr][col] = v;
            }
        }
        // weights: 4*8*9 = 288 (co fastest within pair layout)
        {
            float* sWf = (float*)sW2;
            for (int i = tid; i < 288; i += 128) {
                int cc  = i / 72;
                int rem = i - cc * 72;
                int co  = rem / 9;
                int k   = rem - co * 9;
                float wv = 0.f;
                if (co0 + co < COUT)
                    wv = wt[((size_t)(co0 + co) * CIN + ci0 + cc) * 9 + k];
                sWf[(cc * 9 + k) * 8 + co] = wv;
            }
        }
        __syncthreads();

#pragma unroll
        for (int cc = 0; cc < 4; cc++) {
            u64 pb[4][3];
#pragma unroll
            for (int dr = 0; dr < 4; dr++)
#pragma unroll
                for (int dc = 0; dc < 3; dc++) {
                    float v = sPatch[cc][ry + dr][lx + dc];
                    pb[dr][dc] = pack2(v, v);
                }
#pragma unroll
            for (int ky = 0; ky < 3; ky++)
#pragma unroll
                for (int kx = 0; kx < 3; kx++) {
                    const u64* w2p = (const u64*)sW2[cc][ky * 3 + kx];
#pragma unroll
                    for (int co2 = 0; co2 < 4; co2++) {
                        u64 w = w2p[co2];                 // LDS.64 broadcast
                        ffma2(acc2[co2][0], w, pb[ky][kx]);
                        ffma2(acc2[co2][1], w, pb[ky + 1][kx]);
                    }
                }
        }
    }

#pragma unroll
    for (int co2 = 0; co2 < 4; co2++) {
#pragma unroll
        for (int px = 0; px < 2; px++) {
            float2 v = unpack2(acc2[co2][px]);
            int gy = ty0 + ry + px;
            int coA = co0 + co2 * 2;
            if (coA < COUT)
                out[(((size_t)n * COUT + coA) * H_ + gy) * W_ + tx0 + lx] = v.x + bias[coA];
            if (coA + 1 < COUT)
                out[(((size_t)n * COUT + coA + 1) * H_ + gy) * W_ + tx0 + lx] = v.y + bias[coA + 1];
        }
    }
}

// ============================================================================
// Deformable conv, fused gate epilogues, f32x2-packed over cout pairs.
// 16 couts per block (8 pairs); weights in 72KB dynamic smem, co-pair packed.
// Input: 128-ch concat (inA: 0..63, inB: 64..127).
// MODE 0: out = sigmoid(acc+b)   MODE 1: out = (1-z)*t + z*tanh(acc+b)
// Block: 128 threads = 16x8 pixel tile.
// ============================================================================
template<int MODE>
__global__ __launch_bounds__(128)
void dcn_kernel(const float* __restrict__ inA, const float* __restrict__ inB,
                const float* __restrict__ om,
                const float* __restrict__ wt, const float* __restrict__ bias,
                const float* __restrict__ tbuf, const float* __restrict__ zbuf,
                float* __restrict__ out)
{
    extern __shared__ float sWf[];          // 16*1152 floats = 73728 B
    const int n    = blockIdx.z;
    const int co0  = blockIdx.y * 16;
    const int tile = blockIdx.x;            // 72 tiles (6 x, 12 y)
    const int tx0  = (tile % 6) * 16;
    const int ty0  = (tile / 6) * 8;
    const int tid  = threadIdx.x;
    const int x    = tx0 + (tid & 15);
    const int y    = ty0 + (tid >> 4);
    const int p    = y * W_ + x;

    // stage weights: wt[(co0+co)*1152 + ck] -> sWf[ck*16 + co] (pairs contiguous)
    for (int i = tid; i < 16 * 1152; i += 128) {
        int co = i / 1152;
        int ck = i - co * 1152;
        sWf[ck * 16 + co] = wt[(size_t)(co0 + co) * 1152 + ck];
    }
    __syncthreads();

    u64 acc2[8];
#pragma unroll
    for (int i = 0; i < 8; i++) acc2[i] = 0ull;

    const float* baseOm = om + (size_t)n * 27 * HWp + p;
    const float* pA = inA + (size_t)n * 64 * HWp;
    const float* pB = inB + (size_t)n * 64 * HWp;

#pragma unroll
    for (int k = 0; k < 9; k++) {
        const int ky = k / 3 - 1;
        const int kx = k % 3 - 1;
        float dy = baseOm[(size_t)k * HWp];
        float dx = baseOm[(size_t)(9 + k) * HWp];
        float mm = baseOm[(size_t)(18 + k) * HWp];
        float mask = 1.f / (1.f + __expf(-mm));

        float py = (float)(y + ky) + dy;
        float px = (float)(x + kx) + dx;
        float y0f = floorf(py), x0f = floorf(px);
        float wy = py - y0f, wx = px - x0f;
        int y0 = (int)y0f, x0 = (int)x0f;
        int y1 = y0 + 1, x1 = x0 + 1;
        bool vy0 = (y0 >= 0) & (y0 < H_);
        bool vy1 = (y1 >= 0) & (y1 < H_);
        bool vx0 = (x0 >= 0) & (x0 < W_);
        bool vx1 = (x1 >= 0) & (x1 < W_);
        int yc0 = min(max(y0, 0), H_ - 1), yc1 = min(max(y1, 0), H_ - 1);
        int xc0 = min(max(x0, 0), W_ - 1), xc1 = min(max(x1, 0), W_ - 1);
        int i00 = yc0 * W_ + xc0, i01 = yc0 * W_ + xc1;
        int i10 = yc1 * W_ + xc0, i11 = yc1 * W_ + xc1;
        float w00 = (vy0 & vx0) ? (1.f - wy) * (1.f - wx) * mask : 0.f;
        float w01 = (vy0 & vx1) ? (1.f - wy) * wx * mask : 0.f;
        float w10 = (vy1 & vx0) ? wy * (1.f - wx) * mask : 0.f;
        float w11 = (vy1 & vx1) ? wy * wx * mask : 0.f;

        const float* a00 = pA + i00; const float* a01 = pA + i01;
        const float* a10 = pA + i10; const float* a11 = pA + i11;
#pragma unroll 4
        for (int c = 0; c < 64; c++) {
            float s = w00 * a00[(size_t)c * HWp] + w01 * a01[(size_t)c * HWp]
                    + w10 * a10[(size_t)c * HWp] + w11 * a11[(size_t)c * HWp];
            u64 ss = pack2(s, s);
            const u64* w2 = (const u64*)(sWf + (size_t)(c * 9 + k) * 16);
#pragma unroll
            for (int j = 0; j < 8; j++) ffma2(acc2[j], w2[j], ss);
        }
        const float* b00 = pB + i00; const float* b01 = pB + i01;
        const float* b10 = pB + i10; const float* b11 = pB + i11;
#pragma unroll 4
        for (int c = 0; c < 64; c++) {
            float s = w00 * b00[(size_t)c * HWp] + w01 * b01[(size_t)c * HWp]
                    + w10 * b10[(size_t)c * HWp] + w11 * b11[(size_t)c * HWp];
            u64 ss = pack2(s, s);
            const u64* w2 = (const u64*)(sWf + (size_t)((c + 64) * 9 + k) * 16);
#pragma unroll
            for (int j = 0; j < 8; j++) ffma2(acc2[j], w2[j], ss);
        }
    }

#pragma unroll
    for (int j = 0; j < 8; j++) {
        float2 v2 = unpack2(acc2[j]);
        float vv[2] = {v2.x, v2.y};
#pragma unroll
        for (int h = 0; h < 2; h++) {
            int co = co0 + j * 2 + h;
            float v = vv[h] + bias[co];
            size_t oi = ((size_t)n * 64 + co) * HWp + p;
            if (MODE == 0) {
                out[oi] = 1.f / (1.f + __expf(-v));
            } else {
                float zv = zbuf[oi];
                float tv = tbuf[oi];
                out[oi] = (1.f - zv) * tv + zv * tanhf(v);
            }
        }
    }
}

// ============================================================================
// ncf: 7x7 (radius 3, dilation 2) correlation + softmax + sample.
// Block: 256 threads, 16x8 pixel tile; 2 threads/pixel split channels 32/32.
// f2 tile (with zero halo, = reference zero-padding) staged in smem per
// 8-channel chunk; two buffers so both halves work every iteration.
// Dynamic smem: tiles 8960 floats (aliased by corr-exchange 6272) + weights 6272.
// ============================================================================
__global__ __launch_bounds__(256)
void ncf_kernel(const float* __restrict__ f1, const float* __restrict__ f2,
                float* __restrict__ r)
{
    extern __shared__ float sm[];
    float* sTile = sm;                 // [2][8][20][28] = 8960 floats
    float* sExch = sm;                 // alias: [128][49] = 6272 floats
    float* sWgt  = sm + 8960;          // [128][49] = 6272 floats

    const int n    = blockIdx.y;
    const int tile = blockIdx.x;       // 72 tiles (6 x, 12 y)
    const int tx0  = (tile % 6) * 16;
    const int ty0  = (tile / 6) * 8;
    const int tid  = threadIdx.x;
    const int pix  = tid & 127;
    const int half = tid >> 7;
    const int lx   = pix & 15;
    const int ly   = pix >> 4;
    const int x    = tx0 + lx;
    const int y    = ty0 + ly;
    const int p    = y * W_ + x;

    const float* F1 = f1 + (size_t)n * 64 * HWp;
    const float* F2 = f2 + (size_t)n * 64 * HWp;

    float corr[49];
#pragma unroll
    for (int k = 0; k < 49; k++) corr[k] = 0.f;

    // ---- correlation phase ----
    for (int j = 0; j < 4; j++) {
        __syncthreads();
        // load chunk j (half0 channels) and chunk 4+j (half1 channels): 8960 elems
        for (int i = tid; i < 8960; i += 256) {
            int hb  = i / 4480;
            int rem = i - hb * 4480;
            int c   = rem / 560;
            int rc  = rem - c * 560;
            int rr  = rc / 28;
            int col = rc - rr * 28;
            int gy = ty0 + rr - 6, gx = tx0 + col - 6;
            int gc = hb * 32 + j * 8 + c;
            float v = 0.f;
            if ((unsigned)gy < (unsigned)H_ && (unsigned)gx < (unsigned)W_)
                v = F2[(size_t)gc * HWp + gy * W_ + gx];
            sTile[i] = v;
        }
        __syncthreads();
        const float* myT = sTile + half * 4480;
#pragma unroll
        for (int c = 0; c < 8; c++) {
            float f1v = F1[(size_t)(half * 32 + j * 8 + c) * HWp + p];
            const float* trow = myT + c * 560 + ly * 28 + lx;
#pragma unroll
            for (int k = 0; k < 49; k++)
                corr[k] += f1v * trow[(k / 7) * 56 + (k % 7) * 2];
        }
    }

    // ---- exchange + softmax (over all 49 taps; zeros at OOB match padding) ----
    __syncthreads();
    if (half == 1) {
#pragma unroll
        for (int k = 0; k < 49; k++) sExch[pix * 49 + k] = corr[k];
    }
    __syncthreads();
    if (half == 0) {
        float tot[49];
        float m = -1e30f;
#pragma unroll
        for (int k = 0; k < 49; k++) {
            tot[k] = (corr[k] + sExch[pix * 49 + k]) * 0.125f;   // 1/sqrt(64)
            m = fmaxf(m, tot[k]);
        }
        float sum = 0.f;
#pragma unroll
        for (int k = 0; k < 49; k++) { tot[k] = __expf(tot[k] - m); sum += tot[k]; }
        float inv = 1.f / sum;
#pragma unroll
        for (int k = 0; k < 49; k++) sWgt[pix * 49 + k] = tot[k] * inv;
    }
    __syncthreads();

    float w[49];
#pragma unroll
    for (int k = 0; k < 49; k++) w[k] = sWgt[pix * 49 + k];

    // ---- sample phase ----
    for (int j = 0; j < 4; j++) {
        __syncthreads();
        for (int i = tid; i < 8960; i += 256) {
            int hb  = i / 4480;
            int rem = i - hb * 4480;
            int c   = rem / 560;
            int rc  = rem - c * 560;
            int rr  = rc / 28;
            int col = rc - rr * 28;
            int gy = ty0 + rr - 6, gx = tx0 + col - 6;
            int gc = hb * 32 + j * 8 + c;
            float v = 0.f;
            if ((unsigned)gy < (unsigned)H_ && (unsigned)gx < (unsigned)W_)
                v = F2[(size_t)gc * HWp + gy * W_ + gx];
            sTile[i] = v;
        }
        __syncthreads();
        const float* myT = sTile + half * 4480;
#pragma unroll
        for (int c = 0; c < 8; c++) {
            const float* trow = myT + c * 560 + ly * 28 + lx;
            float s = 0.f;
#pragma unroll
            for (int k = 0; k < 49; k++)
                s += w[k] * trow[(k / 7) * 56 + (k % 7) * 2];
            r[((size_t)n * 64 + half * 32 + j * 8 + c) * HWp + p] = s;
        }
    }
}

// ============================================================================
// launch
// ============================================================================
extern "C" void kernel_launch(void* const* d_in, const int* in_sizes, int n_in,
                              void* d_out, int out_size)
{
    (void)in_sizes; (void)n_in; (void)out_size;
    const float* x    = (const float*)d_in[0];
    const float* tmpl = (const float*)d_in[1];
    const float* w_in = (const float*)d_in[2];
    const float* b_in = (const float*)d_in[3];
    const float* w_out= (const float*)d_in[4];
    const float* b_out= (const float*)d_in[5];
    const float* ezw  = (const float*)d_in[6];
    const float* ezb  = (const float*)d_in[7];
    const float* ezow = (const float*)d_in[8];
    const float* ezob = (const float*)d_in[9];
    const float* ehw  = (const float*)d_in[10];
    const float* ehb  = (const float*)d_in[11];
    const float* ehow = (const float*)d_in[12];
    const float* ehob = (const float*)d_in[13];
    const float* uzw  = (const float*)d_in[14];
    const float* uzb  = (const float*)d_in[15];
    const float* uzow = (const float*)d_in[16];
    const float* uzob = (const float*)d_in[17];
    const float* uhw  = (const float*)d_in[18];
    const float* uhb  = (const float*)d_in[19];
    const float* uhow = (const float*)d_in[20];
    const float* uhob = (const float*)d_in[21];

    float *xh, *om, *z, *r, *xenh;
    cudaGetSymbolAddress((void**)&xh,   g_xh);
    cudaGetSymbolAddress((void**)&om,   g_om);
    cudaGetSymbolAddress((void**)&z,    g_z);
    cudaGetSymbolAddress((void**)&r,    g_r);
    cudaGetSymbolAddress((void**)&xenh, g_xenh);

    float* out_main = (float*)d_out;                       // (2,256,96,96)
    float* out_nt   = out_main + (size_t)N_ * 256 * HWp;   // (2,64,96,96)

    const int DCN_SMEM = 16 * 1152 * 4;                    // 73728
    const int NCF_SMEM = (8960 + 6272) * 4;                // 60928
    cudaFuncSetAttribute(dcn_kernel<0>, cudaFuncAttributeMaxDynamicSharedMemorySize, DCN_SMEM);
    cudaFuncSetAttribute(dcn_kernel<1>, cudaFuncAttributeMaxDynamicSharedMemorySize, DCN_SMEM);
    cudaFuncSetAttribute(ncf_kernel,    cudaFuncAttributeMaxDynamicSharedMemorySize, NCF_SMEM);

    dim3 blk(128);

    // xh = conv_in(x)
    conv3x3_kernel<256,256><<<dim3(36, 8, 2), blk>>>(x, x, w_in, b_in, xh, 64);

    // ---- stargru enh: x = template, t = xh ----
    conv3x3_kernel<128,64><<<dim3(36, 4, 2), blk>>>(tmpl, xh, ezow, ezob, om, 27);
    dcn_kernel<0><<<dim3(72, 4, 2), blk, DCN_SMEM>>>(tmpl, xh, om, ezw, ezb, nullptr, nullptr, z);
    ncf_kernel<<<dim3(72, 2), dim3(256), NCF_SMEM>>>(xh, tmpl, r);
    conv3x3_kernel<128,64><<<dim3(36, 4, 2), blk>>>(r, xh, ehow, ehob, om, 27);
    dcn_kernel<1><<<dim3(72, 4, 2), blk, DCN_SMEM>>>(r, xh, om, ehw, ehb, xh, z, xenh);

    // ---- stargru upd: x = xh, t = template ----
    conv3x3_kernel<128,64><<<dim3(36, 4, 2), blk>>>(xh, tmpl, uzow, uzob, om, 27);
    dcn_kernel<0><<<dim3(72, 4, 2), blk, DCN_SMEM>>>(xh, tmpl, om, uzw, uzb, nullptr, nullptr, z);
    ncf_kernel<<<dim3(72, 2), dim3(256), NCF_SMEM>>>(tmpl, xh, r);
    conv3x3_kernel<128,64><<<dim3(36, 4, 2), blk>>>(r, tmpl, uhow, uhob, om, 27);
    dcn_kernel<1><<<dim3(72, 4, 2), blk, DCN_SMEM>>>(r, tmpl, om, uhw, uhb, tmpl, z, out_nt);

    // out = conv_out(x_enh)
    conv3x3_kernel<64,64><<<dim3(36, 32, 2), blk>>>(xenh, xenh, w_out, b_out, out_main, 256);
}

// round 6
// speedup vs baseline: 1.7438x; 1.3927x over previous
#include <cuda_runtime.h>
#include <cuda_bf16.h>
#include <math.h>

#define N_   2
#define H_   96
#define W_   96
#define HWp  9216      // H_*W_

typedef unsigned long long u64;

__device__ __forceinline__ u64 pack2(float lo, float hi) {
    u64 r; asm("mov.b64 %0, {%1, %2};" : "=l"(r) : "f"(lo), "f"(hi)); return r;
}
__device__ __forceinline__ void ffma2(u64 &d, u64 a, u64 b) {
    asm("fma.rn.f32x2 %0, %1, %2, %0;" : "+l"(d) : "l"(a), "l"(b));
}
__device__ __forceinline__ float2 unpack2(u64 v) {
    float2 f; asm("mov.b64 {%0, %1}, %2;" : "=f"(f.x), "=f"(f.y) : "l"(v)); return f;
}

// ---------------- scratch (device globals; allocation-free) ----------------
__device__ float g_xh   [N_*64*HWp];
__device__ float g_xhT  [N_*HWp*64];     // NHWC
__device__ float g_tmplT[N_*HWp*64];     // NHWC
__device__ float g_om_ze[N_*27*HWp];
__device__ float g_om_zu[N_*27*HWp];
__device__ float g_om_he[N_*27*HWp];
__device__ float g_om_hu[N_*27*HWp];
__device__ float g_ze   [N_*64*HWp];
__device__ float g_zu   [N_*64*HWp];
__device__ float g_re   [N_*64*HWp];
__device__ float g_ru   [N_*64*HWp];
__device__ float g_reT  [N_*HWp*64];     // NHWC
__device__ float g_ruT  [N_*HWp*64];     // NHWC
__device__ float g_xenh [N_*64*HWp];

// ============================================================================
// NCHW -> NHWC transpose (64 channels). 64 threads: lanes = channels.
// ============================================================================
__global__ __launch_bounds__(64)
void transpose_nhwc_kernel(const float* __restrict__ in, float* __restrict__ out)
{
    const int n = blockIdx.y;
    const int y = blockIdx.x;
    const int c = (int)threadIdx.x;      // 0..63
    const float* src = in  + ((size_t)n * 64 + c) * HWp + y * W_;
    float*       dst = out + ((size_t)n * HWp + y * W_) * 64 + c;
#pragma unroll 4
    for (int x = 0; x < W_; x++)
        dst[(size_t)x * 64] = src[x];
}

// ============================================================================
// conv3x3, SAME, NCHW, f32x2 over cout pairs. Chain-merged via args structs.
// Block: 128 threads, 32x8 tile, 8 couts (4 pairs), 2 vertical px/thread.
// Optional NHWC dual output (COUT==64 only).
// ============================================================================
struct ConvArgs {
    const float *inA, *inB, *wt, *bias;
    float *out, *out_nhwc;
};

template<int CIN, int CA>
__global__ __launch_bounds__(128)
void conv3x3_kernel(ConvArgs a0, ConvArgs a1, int COUT)
{
    const int chain = blockIdx.z >> 1;
    const int n     = blockIdx.z & 1;
    const ConvArgs A = chain ? a1 : a0;

    const int tile = blockIdx.x;            // 36 tiles: 3 x, 12 y
    const int co0  = blockIdx.y * 8;
    const int tx0  = (tile % 3) * 32;
    const int ty0  = (tile / 3) * 8;
    const int tid  = threadIdx.x;
    const int lx   = tid & 31;
    const int ry   = (tid >> 5) * 2;

    __shared__ float  sPatch[4][10][36];
    __shared__ float2 sW2[4][9][4];

    u64 acc2[4][2];
#pragma unroll
    for (int i = 0; i < 4; i++) { acc2[i][0] = 0ull; acc2[i][1] = 0ull; }

    for (int ci0 = 0; ci0 < CIN; ci0 += 4) {
        __syncthreads();
#pragma unroll
        for (int it = 0; it < 11; it++) {
            int idx = tid + it * 128;
            if (idx < 1360) {
                int cc  = idx / 340;
                int rem = idx - cc * 340;
                int rr  = rem / 34;
                int col = rem - rr * 34;
                int gy = ty0 + rr - 1;
                int gx = tx0 + col - 1;
                float v = 0.f;
                if ((unsigned)gy < (unsigned)H_ && (unsigned)gx < (unsigned)W_) {
                    int c = ci0 + cc;
                    const float* src = (c < CA)
                        ? A.inA + ((size_t)n * CA + c) * HWp
                        : A.inB + ((size_t)n * (CIN - CA) + (c - CA)) * HWp;
                    v = src[gy * W_ + gx];
                }
                sPatch[cc][rr][col] = v;
            }
        }
        {
            float* sWf = (float*)sW2;
            for (int i = tid; i < 288; i += 128) {
                int cc  = i / 72;
                int rem = i - cc * 72;
                int co  = rem / 9;
                int k   = rem - co * 9;
                float wv = 0.f;
                if (co0 + co < COUT)
                    wv = A.wt[((size_t)(co0 + co) * CIN + ci0 + cc) * 9 + k];
                sWf[(cc * 9 + k) * 8 + co] = wv;
            }
        }
        __syncthreads();

#pragma unroll
        for (int cc = 0; cc < 4; cc++) {
            u64 pb[4][3];
#pragma unroll
            for (int dr = 0; dr < 4; dr++)
#pragma unroll
                for (int dc = 0; dc < 3; dc++) {
                    float v = sPatch[cc][ry + dr][lx + dc];
                    pb[dr][dc] = pack2(v, v);
                }
#pragma unroll
            for (int ky = 0; ky < 3; ky++)
#pragma unroll
                for (int kx = 0; kx < 3; kx++) {
                    const u64* w2p = (const u64*)sW2[cc][ky * 3 + kx];
#pragma unroll
                    for (int co2 = 0; co2 < 4; co2++) {
                        u64 w = w2p[co2];
                        ffma2(acc2[co2][0], w, pb[ky][kx]);
                        ffma2(acc2[co2][1], w, pb[ky + 1][kx]);
                    }
                }
        }
    }

#pragma unroll
    for (int px = 0; px < 2; px++) {
        float v[8];
#pragma unroll
        for (int co2 = 0; co2 < 4; co2++) {
            float2 t = unpack2(acc2[co2][px]);
            int coA = co0 + co2 * 2;
            v[co2 * 2]     = t.x + ((coA     < COUT) ? A.bias[coA]     : 0.f);
            v[co2 * 2 + 1] = t.y + ((coA + 1 < COUT) ? A.bias[coA + 1] : 0.f);
        }
        int gy = ty0 + ry + px;
        int gp = gy * W_ + tx0 + lx;
#pragma unroll
        for (int co = 0; co < 8; co++)
            if (co0 + co < COUT)
                A.out[((size_t)n * COUT + co0 + co) * HWp + gp] = v[co];
        if (A.out_nhwc) {   // COUT==64 path
            float* dst = A.out_nhwc + ((size_t)n * HWp + gp) * 64 + co0;
            *(float4*)dst       = make_float4(v[0], v[1], v[2], v[3]);
            *(float4*)(dst + 4) = make_float4(v[4], v[5], v[6], v[7]);
        }
    }
}

// ============================================================================
// Deformable conv, chain-merged, fused gate epilogues.
// Gather sources A,B are NHWC (64 ch each). 32 couts/block (blockIdx.y: 2).
// 2 pixels/thread packed in f32x2 lanes; weights (w,w)-duplicated, staged
// per-k in 32KB smem. Block: 128 thr = 16x16 pixel tile (2 rows/thread).
// MODE 0: out = sigmoid(acc+b).  MODE 1: out = (1-z)*t + z*tanh(acc+b).
// ============================================================================
struct DcnArgs {
    const float *A, *B;          // NHWC gather sources
    const float *om;             // NCHW, 27 ch
    const float *wt, *bias;      // (64,128,9), (64)
    const float *t, *z;          // NCHW (MODE 1)
    float *out;                  // NCHW
};

template<int MODE>
__global__ __launch_bounds__(128)
void dcn_kernel(DcnArgs d0, DcnArgs d1)
{
    __shared__ u64 sW[128 * 32];            // 32 KB
    const int chain = blockIdx.z >> 1;
    const int n     = blockIdx.z & 1;
    const DcnArgs a = chain ? d1 : d0;
    const int co0  = blockIdx.y * 32;
    const int tile = blockIdx.x;            // 36 tiles (6 x, 6 y) of 16x16
    const int tx0  = (tile % 6) * 16;
    const int ty0  = (tile / 6) * 16;
    const int tid  = threadIdx.x;
    const int lx   = tid & 15;
    const int x    = tx0 + lx;
    const int y0   = ty0 + (tid >> 4) * 2;
    const int p0   = y0 * W_ + x;
    const int p1   = p0 + W_;

    u64 acc[32];
#pragma unroll
    for (int i = 0; i < 32; i++) acc[i] = 0ull;

    const float* om = a.om + (size_t)n * 27 * HWp;
    const float* Ap = a.A  + (size_t)n * HWp * 64;
    const float* Bp = a.B  + (size_t)n * HWp * 64;

    for (int k = 0; k < 9; k++) {
        __syncthreads();
        for (int i = tid; i < 4096; i += 128) {
            int c  = i >> 5;
            int co = i & 31;
            float w = a.wt[(size_t)(co0 + co) * 1152 + c * 9 + k];
            sW[c * 32 + co] = pack2(w, w);
        }
        __syncthreads();

        const int ky = k / 3 - 1, kx = k % 3 - 1;
        int   o00[2], o01[2], o10[2], o11[2];
        float W00[2], W01[2], W10[2], W11[2];
#pragma unroll
        for (int pp = 0; pp < 2; pp++) {
            int yy = y0 + pp;
            int P  = yy * W_ + x;
            float dy = om[(size_t)k * HWp + P];
            float dx = om[(size_t)(9 + k) * HWp + P];
            float mm = om[(size_t)(18 + k) * HWp + P];
            float mask = 1.f / (1.f + __expf(-mm));
            float py = (float)(yy + ky) + dy;
            float px = (float)(x + kx) + dx;
            float y0f = floorf(py), x0f = floorf(px);
            float wy = py - y0f, wx = px - x0f;
            int iy0 = (int)y0f, ix0 = (int)x0f;
            int iy1 = iy0 + 1,  ix1 = ix0 + 1;
            bool vy0 = (iy0 >= 0) & (iy0 < H_);
            bool vy1 = (iy1 >= 0) & (iy1 < H_);
            bool vx0 = (ix0 >= 0) & (ix0 < W_);
            bool vx1 = (ix1 >= 0) & (ix1 < W_);
            int yc0 = min(max(iy0, 0), H_ - 1), yc1 = min(max(iy1, 0), H_ - 1);
            int xc0 = min(max(ix0, 0), W_ - 1), xc1 = min(max(ix1, 0), W_ - 1);
            o00[pp] = (yc0 * W_ + xc0) * 64;  o01[pp] = (yc0 * W_ + xc1) * 64;
            o10[pp] = (yc1 * W_ + xc0) * 64;  o11[pp] = (yc1 * W_ + xc1) * 64;
            W00[pp] = (vy0 & vx0) ? (1.f - wy) * (1.f - wx) * mask : 0.f;
            W01[pp] = (vy0 & vx1) ? (1.f - wy) * wx * mask : 0.f;
            W10[pp] = (vy1 & vx0) ? wy * (1.f - wx) * mask : 0.f;
            W11[pp] = (vy1 & vx1) ? wy * wx * mask : 0.f;
        }

#pragma unroll 2
        for (int cc = 0; cc < 32; cc++) {
            const float* base = (cc < 16) ? (Ap + cc * 4) : (Bp + (cc - 16) * 4);
            float sv[2][4];
#pragma unroll
            for (int pp = 0; pp < 2; pp++) {
                float4 v00 = *(const float4*)(base + o00[pp]);
                float4 v01 = *(const float4*)(base + o01[pp]);
                float4 v10 = *(const float4*)(base + o10[pp]);
                float4 v11 = *(const float4*)(base + o11[pp]);
                sv[pp][0] = W00[pp]*v00.x + W01[pp]*v01.x + W10[pp]*v10.x + W11[pp]*v11.x;
                sv[pp][1] = W00[pp]*v00.y + W01[pp]*v01.y + W10[pp]*v10.y + W11[pp]*v11.y;
                sv[pp][2] = W00[pp]*v00.z + W01[pp]*v01.z + W10[pp]*v10.z + W11[pp]*v11.z;
                sv[pp][3] = W00[pp]*v00.w + W01[pp]*v01.w + W10[pp]*v10.w + W11[pp]*v11.w;
            }
            const u64* wr = sW + (cc * 4) * 32;
#pragma unroll
            for (int ch = 0; ch < 4; ch++) {
                u64 ss = pack2(sv[0][ch], sv[1][ch]);
                const u64* w = wr + ch * 32;
#pragma unroll
                for (int co = 0; co < 32; co++) ffma2(acc[co], w[co], ss);
            }
        }
    }

#pragma unroll
    for (int co = 0; co < 32; co++) {
        float2 v = unpack2(acc[co]);
        float b = a.bias[co0 + co];
        float vv[2] = {v.x + b, v.y + b};
        size_t oi0 = ((size_t)n * 64 + co0 + co) * HWp;
#pragma unroll
        for (int pp = 0; pp < 2; pp++) {
            size_t oi = oi0 + (pp ? p1 : p0);
            if (MODE == 0) {
                a.out[oi] = 1.f / (1.f + __expf(-vv[pp]));
            } else {
                float zv = a.z[oi];
                float tv = a.t[oi];
                a.out[oi] = (1.f - zv) * tv + zv * tanhf(vv[pp]);
            }
        }
    }
}

// ============================================================================
// ncf: 7x7 (radius 3, dilation 2) correlation + softmax + sample. Chain-merged.
// Block: 256 threads, 16x8 pixel tile; 2 threads/pixel split channels 32/32.
// Dual output: NCHW + NHWC.
// ============================================================================
struct NcfArgs {
    const float *f1, *f2;
    float *out, *out_nhwc;
};

__global__ __launch_bounds__(256)
void ncf_kernel(NcfArgs a0, NcfArgs a1)
{
    extern __shared__ float sm[];
    float* sTile = sm;                 // [2][8][20][28] = 8960 floats
    float* sExch = sm;                 // alias: [128][49] = 6272 floats
    float* sWgt  = sm + 8960;          // [128][49] = 6272 floats

    const int chain = blockIdx.y >> 1;
    const int n     = blockIdx.y & 1;
    const NcfArgs A = chain ? a1 : a0;

    const int tile = blockIdx.x;       // 72 tiles (6 x, 12 y)
    const int tx0  = (tile % 6) * 16;
    const int ty0  = (tile / 6) * 8;
    const int tid  = threadIdx.x;
    const int pix  = tid & 127;
    const int half = tid >> 7;
    const int lx   = pix & 15;
    const int ly   = pix >> 4;
    const int x    = tx0 + lx;
    const int y    = ty0 + ly;
    const int p    = y * W_ + x;

    const float* F1 = A.f1 + (size_t)n * 64 * HWp;
    const float* F2 = A.f2 + (size_t)n * 64 * HWp;

    float corr[49];
#pragma unroll
    for (int k = 0; k < 49; k++) corr[k] = 0.f;

    for (int j = 0; j < 4; j++) {
        __syncthreads();
        for (int i = tid; i < 8960; i += 256) {
            int hb  = i / 4480;
            int rem = i - hb * 4480;
            int c   = rem / 560;
            int rc  = rem - c * 560;
            int rr  = rc / 28;
            int col = rc - rr * 28;
            int gy = ty0 + rr - 6, gx = tx0 + col - 6;
            int gc = hb * 32 + j * 8 + c;
            float v = 0.f;
            if ((unsigned)gy < (unsigned)H_ && (unsigned)gx < (unsigned)W_)
                v = F2[(size_t)gc * HWp + gy * W_ + gx];
            sTile[i] = v;
        }
        __syncthreads();
        const float* myT = sTile + half * 4480;
#pragma unroll
        for (int c = 0; c < 8; c++) {
            float f1v = F1[(size_t)(half * 32 + j * 8 + c) * HWp + p];
            const float* trow = myT + c * 560 + ly * 28 + lx;
#pragma unroll
            for (int k = 0; k < 49; k++)
                corr[k] += f1v * trow[(k / 7) * 56 + (k % 7) * 2];
        }
    }

    __syncthreads();
    if (half == 1) {
#pragma unroll
        for (int k = 0; k < 49; k++) sExch[pix * 49 + k] = corr[k];
    }
    __syncthreads();
    if (half == 0) {
        float tot[49];
        float m = -1e30f;
#pragma unroll
        for (int k = 0; k < 49; k++) {
            tot[k] = (corr[k] + sExch[pix * 49 + k]) * 0.125f;
            m = fmaxf(m, tot[k]);
        }
        float sum = 0.f;
#pragma unroll
        for (int k = 0; k < 49; k++) { tot[k] = __expf(tot[k] - m); sum += tot[k]; }
        float inv = 1.f / sum;
#pragma unroll
        for (int k = 0; k < 49; k++) sWgt[pix * 49 + k] = tot[k] * inv;
    }
    __syncthreads();

    float w[49];
#pragma unroll
    for (int k = 0; k < 49; k++) w[k] = sWgt[pix * 49 + k];

    for (int j = 0; j < 4; j++) {
        __syncthreads();
        for (int i = tid; i < 8960; i += 256) {
            int hb  = i / 4480;
            int rem = i - hb * 4480;
            int c   = rem / 560;
            int rc  = rem - c * 560;
            int rr  = rc / 28;
            int col = rc - rr * 28;
            int gy = ty0 + rr - 6, gx = tx0 + col - 6;
            int gc = hb * 32 + j * 8 + c;
            float v = 0.f;
            if ((unsigned)gy < (unsigned)H_ && (unsigned)gx < (unsigned)W_)
                v = F2[(size_t)gc * HWp + gy * W_ + gx];
            sTile[i] = v;
        }
        __syncthreads();
        const float* myT = sTile + half * 4480;
        float res[8];
#pragma unroll
        for (int c = 0; c < 8; c++) {
            const float* trow = myT + c * 560 + ly * 28 + lx;
            float s = 0.f;
#pragma unroll
            for (int k = 0; k < 49; k++)
                s += w[k] * trow[(k / 7) * 56 + (k % 7) * 2];
            res[c] = s;
            A.out[((size_t)n * 64 + half * 32 + j * 8 + c) * HWp + p] = s;
        }
        float* dst = A.out_nhwc + ((size_t)n * HWp + p) * 64 + half * 32 + j * 8;
        *(float4*)dst       = make_float4(res[0], res[1], res[2], res[3]);
        *(float4*)(dst + 4) = make_float4(res[4], res[5], res[6], res[7]);
    }
}

// ============================================================================
// launch
// ============================================================================
extern "C" void kernel_launch(void* const* d_in, const int* in_sizes, int n_in,
                              void* d_out, int out_size)
{
    (void)in_sizes; (void)n_in; (void)out_size;
    const float* x    = (const float*)d_in[0];
    const float* tmpl = (const float*)d_in[1];
    const float* w_in = (const float*)d_in[2];
    const float* b_in = (const float*)d_in[3];
    const float* w_out= (const float*)d_in[4];
    const float* b_out= (const float*)d_in[5];
    const float* ezw  = (const float*)d_in[6];
    const float* ezb  = (const float*)d_in[7];
    const float* ezow = (const float*)d_in[8];
    const float* ezob = (const float*)d_in[9];
    const float* ehw  = (const float*)d_in[10];
    const float* ehb  = (const float*)d_in[11];
    const float* ehow = (const float*)d_in[12];
    const float* ehob = (const float*)d_in[13];
    const float* uzw  = (const float*)d_in[14];
    const float* uzb  = (const float*)d_in[15];
    const float* uzow = (const float*)d_in[16];
    const float* uzob = (const float*)d_in[17];
    const float* uhw  = (const float*)d_in[18];
    const float* uhb  = (const float*)d_in[19];
    const float* uhow = (const float*)d_in[20];
    const float* uhob = (const float*)d_in[21];

    float *xh, *xhT, *tmplT, *om_ze, *om_zu, *om_he, *om_hu;
    float *ze, *zu, *re, *ru, *reT, *ruT, *xenh;
    cudaGetSymbolAddress((void**)&xh,    g_xh);
    cudaGetSymbolAddress((void**)&xhT,   g_xhT);
    cudaGetSymbolAddress((void**)&tmplT, g_tmplT);
    cudaGetSymbolAddress((void**)&om_ze, g_om_ze);
    cudaGetSymbolAddress((void**)&om_zu, g_om_zu);
    cudaGetSymbolAddress((void**)&om_he, g_om_he);
    cudaGetSymbolAddress((void**)&om_hu, g_om_hu);
    cudaGetSymbolAddress((void**)&ze,    g_ze);
    cudaGetSymbolAddress((void**)&zu,    g_zu);
    cudaGetSymbolAddress((void**)&re,    g_re);
    cudaGetSymbolAddress((void**)&ru,    g_ru);
    cudaGetSymbolAddress((void**)&reT,   g_reT);
    cudaGetSymbolAddress((void**)&ruT,   g_ruT);
    cudaGetSymbolAddress((void**)&xenh,  g_xenh);

    float* out_main = (float*)d_out;
    float* out_nt   = out_main + (size_t)N_ * 256 * HWp;

    const int NCF_SMEM = (8960 + 6272) * 4;
    cudaFuncSetAttribute(ncf_kernel, cudaFuncAttributeMaxDynamicSharedMemorySize, NCF_SMEM);

    dim3 blk(128);

    // tmpl -> NHWC
    transpose_nhwc_kernel<<<dim3(H_, 2), 64>>>(tmpl, tmplT);

    // xh = conv_in(x), dual NCHW + NHWC
    {
        ConvArgs a{x, x, w_in, b_in, xh, xhT};
        conv3x3_kernel<256,256><<<dim3(36, 8, 2), blk>>>(a, a, 64);
    }

    // offset convs for z (both chains)
    {
        ConvArgs ae{tmpl, xh, ezow, ezob, om_ze, nullptr};
        ConvArgs au{xh, tmpl, uzow, uzob, om_zu, nullptr};
        conv3x3_kernel<128,64><<<dim3(36, 4, 4), blk>>>(ae, au, 27);
    }

    // ncf (both chains): enh r = ncf(f1=xh, f2=tmpl); upd r = ncf(f1=tmpl, f2=xh)
    {
        NcfArgs ae{xh, tmpl, re, reT};
        NcfArgs au{tmpl, xh, ru, ruT};
        ncf_kernel<<<dim3(72, 4), dim3(256), NCF_SMEM>>>(ae, au);
    }

    // dcn z-gates (both chains)
    {
        DcnArgs de{tmplT, xhT, om_ze, ezw, ezb, nullptr, nullptr, ze};
        DcnArgs du{xhT, tmplT, om_zu, uzw, uzb, nullptr, nullptr, zu};
        dcn_kernel<0><<<dim3(36, 2, 4), blk>>>(de, du);
    }

    // offset convs for h (both chains)
    {
        ConvArgs ae{re, xh, ehow, ehob, om_he, nullptr};
        ConvArgs au{ru, tmpl, uhow, uhob, om_hu, nullptr};
        conv3x3_kernel<128,64><<<dim3(36, 4, 4), blk>>>(ae, au, 27);
    }

    // dcn h + GRU blend (both chains)
    {
        DcnArgs de{reT, xhT, om_he, ehw, ehb, xh, ze, xenh};
        DcnArgs du{ruT, tmplT, om_hu, uhw, uhb, tmpl, zu, out_nt};
        dcn_kernel<1><<<dim3(36, 2, 4), blk>>>(de, du);
    }

    // out = conv_out(x_enh)
    {
        ConvArgs a{xenh, xenh, w_out, b_out, out_main, nullptr};
        conv3x3_kernel<64,64><<<dim3(36, 32, 2), blk>>>(a, a, 256);
    }
}